// round 7
// baseline (speedup 1.0000x reference)
#include <cuda_runtime.h>
#include <math.h>

#define N_NODES 100000
#define N_EDGES 1600000
#define NB_SCAN 98          // ceil(100000 / 1024)

// ---------------------------------------------------------------------------
// Scratch (__device__ globals; no allocations anywhere). Kernels receive all
// pointers as parameters (host resolves via cudaGetSymbolAddress).
// ---------------------------------------------------------------------------
__device__ float4 g_agg4[(size_t)N_NODES * 32];   // 51.2 MB aggregated feats
__device__ float4 g_hA4[(size_t)N_NODES * 32];    // 51.2 MB hidden ping
__device__ float4 g_hB4[(size_t)N_NODES * 32];    // 51.2 MB hidden pong
__device__ int    g_row_[N_NODES + 1];            // CSR row starts
__device__ int    g_csr_[N_EDGES];                // CSR col indices (src)
__device__ int    g_bsum_[NB_SCAN];               // scan block sums
__device__ int    g_flag_[1];                     // 1 = edges are int64, 0 = int32

// ---------------------------------------------------------------------------
// Edge dtype probe: int32 data read as int64 fuses two 32-bit values and is
// >= 2^32 whenever the high word is nonzero; 16 consecutive in-range int64
// reads are overwhelming evidence of genuine int64 data.
// ---------------------------------------------------------------------------
__global__ void detect_kernel(const void* __restrict__ ei, int* __restrict__ flag) {
    if (blockIdx.x == 0 && threadIdx.x == 0) {
        const long long* e64 = (const long long*)ei;
        int is64 = 1;
        for (int i = 0; i < 16; i++) {
            long long v = e64[i];
            if (v < 0 || v >= N_NODES) { is64 = 0; break; }
        }
        *flag = is64;
    }
}

__device__ __forceinline__ int2 load_edge(const void* __restrict__ ei, int e, int is64) {
    if (is64) {
        const long long* p = (const long long*)ei;
        return make_int2((int)p[e], (int)p[N_EDGES + e]);
    } else {
        const int* p = (const int*)ei;
        return make_int2(p[e], p[N_EDGES + e]);
    }
}

// ---------------------------------------------------------------------------
// CSR build. Atomics only on harness-allocated d_out scratch.
// ---------------------------------------------------------------------------
__global__ void zero_int_kernel(int* __restrict__ p, int n) {
    int i = blockIdx.x * blockDim.x + threadIdx.x;
    if (i < n) p[i] = 0;
}

__global__ void hist_kernel(const void* __restrict__ ei,
                            const int* __restrict__ flag,
                            int* __restrict__ cnt) {
    int e = blockIdx.x * blockDim.x + threadIdx.x;
    if (e < N_EDGES) {
        int2 sd = load_edge(ei, e, *flag);
        if ((unsigned)sd.x < N_NODES && (unsigned)sd.y < N_NODES)
            atomicAdd(&cnt[sd.y], 1);
    }
}

// Exclusive scan stage 1: per-1024-block Hillis-Steele
__global__ void scan_block_kernel(const int* __restrict__ cnt,
                                  int* __restrict__ row,
                                  int* __restrict__ bsum) {
    __shared__ int s[1024];
    int i = blockIdx.x * 1024 + threadIdx.x;
    int v = (i < N_NODES) ? cnt[i] : 0;
    s[threadIdx.x] = v;
    __syncthreads();
    for (int off = 1; off < 1024; off <<= 1) {
        int t = (threadIdx.x >= off) ? s[threadIdx.x - off] : 0;
        __syncthreads();
        s[threadIdx.x] += t;
        __syncthreads();
    }
    if (i < N_NODES) row[i] = s[threadIdx.x] - v;   // exclusive
    if (threadIdx.x == 1023) bsum[blockIdx.x] = s[1023];
}

// stage 2: serial exclusive scan of 98 block sums; closes row[N] with total
__global__ void scan_bsum_kernel(int* __restrict__ bsum, int* __restrict__ row) {
    if (threadIdx.x == 0 && blockIdx.x == 0) {
        int acc = 0;
        for (int b = 0; b < NB_SCAN; b++) {
            int t = bsum[b];
            bsum[b] = acc;
            acc += t;
        }
        row[N_NODES] = acc;
    }
}

// stage 3: add block offsets
__global__ void scan_add_kernel(int* __restrict__ row,
                                const int* __restrict__ bsum) {
    int i = blockIdx.x * 1024 + threadIdx.x;
    if (i < N_NODES) row[i] += bsum[blockIdx.x];
}

// cursors := row (cursors live in d_out)
__global__ void copy_int_kernel(const int* __restrict__ src,
                                int* __restrict__ dst, int n) {
    int i = blockIdx.x * blockDim.x + threadIdx.x;
    if (i < n) dst[i] = src[i];
}

// Fill CSR: cursor atomic yields the absolute slot.
__global__ void fill_kernel(const void* __restrict__ ei,
                            const int* __restrict__ flag,
                            int* __restrict__ cur,
                            int* __restrict__ csr) {
    int e = blockIdx.x * blockDim.x + threadIdx.x;
    if (e < N_EDGES) {
        int2 sd = load_edge(ei, e, *flag);
        if ((unsigned)sd.x < N_NODES && (unsigned)sd.y < N_NODES) {
            int pos = atomicAdd(&cur[sd.y], 1);
            if ((unsigned)pos < N_EDGES) csr[pos] = sd.x;
        }
    }
}

// ---------------------------------------------------------------------------
// Pull-mode aggregation: one warp per node, lane l owns float4 at offset 4l.
// Mean folded in. No atomics; 512B coalesced row reads; csr read is a
// warp-uniform broadcast.
// ---------------------------------------------------------------------------
__global__ void gather_kernel(const float4* __restrict__ feat4,
                              const int* __restrict__ row,
                              const int* __restrict__ csr,
                              float4* __restrict__ agg4) {
    int lane = threadIdx.x & 31;
    int n = (blockIdx.x * blockDim.x + threadIdx.x) >> 5;
    if (n >= N_NODES) return;
    int beg = row[n];
    int end = row[n + 1];
    float4 acc = make_float4(0.f, 0.f, 0.f, 0.f);
    for (int i = beg; i < end; i++) {
        int src = csr[i];
        float4 v = feat4[(size_t)src * 32 + lane];
        acc.x += v.x; acc.y += v.y; acc.z += v.z; acc.w += v.w;
    }
    int cnt = end - beg;
    float rd = 1.f / (float)(cnt > 0 ? cnt : 1);
    acc.x *= rd; acc.y *= rd; acc.z *= rd; acc.w *= rd;
    agg4[(size_t)n * 32 + lane] = acc;
}

// ---------------------------------------------------------------------------
// Fused SAGE linear: out = relu( agg @ Wl^T + x @ Wr^T + bl )
// (agg already mean-scaled). Static smem; 64-node tile x full DOUT; KC=16.
// Register tile j = u*TX + tx -> conflict-free weight LDS, coalesced stores.
// ---------------------------------------------------------------------------
template <int DOUT>
__global__ __launch_bounds__(256) void sage_kernel(
    const float* __restrict__ xin,
    const float* __restrict__ aggp,
    const float* __restrict__ Wl, const float* __restrict__ bl,
    const float* __restrict__ Wr,
    float* __restrict__ outp)
{
    constexpr int TM = 64, KC = 16, JT = 8;
    constexpr int TX = DOUT / JT;        // 16 (DOUT=128) or 8 (DOUT=64)
    constexpr int TY = 256 / TX;         // 16 or 32
    constexpr int NPT = TM / TY;         // 4 or 2
    constexpr int WP = DOUT + 4;
    constexpr int AP = TM + 4;

    __shared__ float Wls[KC][WP];
    __shared__ float Wrs[KC][WP];
    __shared__ float Aas[KC][AP];
    __shared__ float Axs[KC][AP];
    __shared__ float bs[DOUT];

    const int t  = threadIdx.x;
    const int tx = t % TX;
    const int ty = t / TX;
    const int base = blockIdx.x * TM;

    if (t < DOUT) bs[t] = bl[t];

    float acc[NPT][JT];
#pragma unroll
    for (int p = 0; p < NPT; p++)
#pragma unroll
        for (int u = 0; u < JT; u++) acc[p][u] = 0.f;

    for (int kc = 0; kc < 128; kc += KC) {
        __syncthreads();
        for (int i = t; i < KC * DOUT; i += 256) {
            int kk = i % KC;
            int j  = i / KC;
            Wls[kk][j] = Wl[j * 128 + kc + kk];
            Wrs[kk][j] = Wr[j * 128 + kc + kk];
        }
        for (int i = t; i < KC * TM; i += 256) {
            int kk = i % KC;
            int n  = i / KC;
            int node = base + n;
            float av = 0.f, xv = 0.f;
            if (node < N_NODES) {
                av = aggp[(size_t)node * 128 + kc + kk];
                xv = xin[(size_t)node * 128 + kc + kk];
            }
            Aas[kk][n] = av;
            Axs[kk][n] = xv;
        }
        __syncthreads();
#pragma unroll
        for (int kk = 0; kk < KC; kk++) {
            float wlv[JT], wrv[JT], av[NPT], xv[NPT];
#pragma unroll
            for (int u = 0; u < JT; u++) {
                wlv[u] = Wls[kk][u * TX + tx];   // consecutive lanes -> consecutive banks
                wrv[u] = Wrs[kk][u * TX + tx];
            }
#pragma unroll
            for (int p = 0; p < NPT; p++) {
                av[p] = Aas[kk][ty * NPT + p];   // warp-uniform broadcast
                xv[p] = Axs[kk][ty * NPT + p];
            }
#pragma unroll
            for (int p = 0; p < NPT; p++)
#pragma unroll
                for (int u = 0; u < JT; u++)
                    acc[p][u] += av[p] * wlv[u] + xv[p] * wrv[u];
        }
    }

#pragma unroll
    for (int p = 0; p < NPT; p++) {
        int node = base + ty * NPT + p;
        if (node < N_NODES) {
#pragma unroll
            for (int u = 0; u < JT; u++) {
                int j = u * TX + tx;
                float v = acc[p][u] + bs[j];
                outp[(size_t)node * DOUT + j] = v > 0.f ? v : 0.f;
            }
        }
    }
}

// ---------------------------------------------------------------------------
// Classifier: sigmoid(h @ Wc^T + bc). One warp per node, 2 features/lane.
// ---------------------------------------------------------------------------
__global__ void cls_kernel(const float* __restrict__ h,
                           const float* __restrict__ Wc,
                           const float* __restrict__ bc,
                           float* __restrict__ outp) {
    int lane = threadIdx.x & 31;
    int n = (blockIdx.x * blockDim.x + threadIdx.x) >> 5;
    if (n >= N_NODES) return;
    float w0 = Wc[lane * 2], w1 = Wc[lane * 2 + 1];
    float b = bc[0];
    const float* hp = h + (size_t)n * 64 + lane * 2;
    float s = hp[0] * w0 + hp[1] * w1;
#pragma unroll
    for (int o = 16; o > 0; o >>= 1) s += __shfl_xor_sync(0xffffffffu, s, o);
    if (lane == 0) outp[n] = 1.f / (1.f + expf(-(s + b)));
}

// ---------------------------------------------------------------------------
// Launch. d_out doubles as int scratch (cnt, then cursors) for the CSR build,
// then is fully overwritten by cls_kernel. Launches only; no host state.
// ---------------------------------------------------------------------------
extern "C" void kernel_launch(void* const* d_in, const int* in_sizes, int n_in,
                              void* d_out, int out_size) {
    const float* x   = (const float*)d_in[0];
    const void*  ei  = d_in[1];               // int32 or int64, probed at runtime
    const float* Wl1 = (const float*)d_in[2];
    const float* bl1 = (const float*)d_in[3];
    const float* Wr1 = (const float*)d_in[4];
    const float* Wl2 = (const float*)d_in[5];
    const float* bl2 = (const float*)d_in[6];
    const float* Wr2 = (const float*)d_in[7];
    const float* Wl3 = (const float*)d_in[8];
    const float* bl3 = (const float*)d_in[9];
    const float* Wr3 = (const float*)d_in[10];
    const float* Wc  = (const float*)d_in[11];
    const float* bc  = (const float*)d_in[12];

    void *p_agg = 0, *p_hA = 0, *p_hB = 0, *p_row = 0, *p_csr = 0, *p_bsum = 0, *p_flag = 0;
    cudaGetSymbolAddress(&p_agg,  g_agg4);
    cudaGetSymbolAddress(&p_hA,   g_hA4);
    cudaGetSymbolAddress(&p_hB,   g_hB4);
    cudaGetSymbolAddress(&p_row,  g_row_);
    cudaGetSymbolAddress(&p_csr,  g_csr_);
    cudaGetSymbolAddress(&p_bsum, g_bsum_);
    cudaGetSymbolAddress(&p_flag, g_flag_);

    float4* agg4 = (float4*)p_agg;
    float4* hA4  = (float4*)p_hA;
    float4* hB4  = (float4*)p_hB;
    float*  aggf = (float*)p_agg;
    float*  hAf  = (float*)p_hA;
    float*  hBf  = (float*)p_hB;
    int*    row  = (int*)p_row;
    int*    csr  = (int*)p_csr;
    int*    bsum = (int*)p_bsum;
    int*    flag = (int*)p_flag;
    int*    scr  = (int*)d_out;          // N ints of harness memory
    float*  out  = (float*)d_out;

    const int EB  = (N_EDGES + 255) / 256;        // 6250
    const int NB  = (N_NODES + 255) / 256;        // 391
    const int WNB = (N_NODES * 32 + 255) / 256;   // 12500 (warp per node)
    const int GMB = (N_NODES + 63) / 64;          // 1563

    // probe edge dtype, then CSR build (atomics only on scr / d_out)
    detect_kernel<<<1, 32>>>(ei, flag);
    zero_int_kernel<<<NB, 256>>>(scr, N_NODES);
    hist_kernel<<<EB, 256>>>(ei, flag, scr);
    scan_block_kernel<<<NB_SCAN, 1024>>>(scr, row, bsum);
    scan_bsum_kernel<<<1, 32>>>(bsum, row);
    scan_add_kernel<<<NB_SCAN, 1024>>>(row, bsum);
    copy_int_kernel<<<NB, 256>>>(row, scr, N_NODES);
    fill_kernel<<<EB, 256>>>(ei, flag, scr, csr);

    // layer 1: x -> hA
    gather_kernel<<<WNB, 256>>>((const float4*)x, row, csr, agg4);
    sage_kernel<128><<<GMB, 256>>>(x, aggf, Wl1, bl1, Wr1, hAf);

    // layer 2: hA -> hB
    gather_kernel<<<WNB, 256>>>(hA4, row, csr, agg4);
    sage_kernel<128><<<GMB, 256>>>(hAf, aggf, Wl2, bl2, Wr2, hBf);

    // layer 3: hB -> hA (DOUT=64, reuses hA storage)
    gather_kernel<<<WNB, 256>>>(hB4, row, csr, agg4);
    sage_kernel<64><<<GMB, 256>>>(hBf, aggf, Wl3, bl3, Wr3, hAf);

    // classifier overwrites d_out (scratch no longer needed)
    cls_kernel<<<WNB, 256>>>(hAf, Wc, bc, out);
}

// round 8
// speedup vs baseline: 1.2570x; 1.2570x over previous
#include <cuda_runtime.h>
#include <math.h>

#define N_NODES 100000
#define N_EDGES 1600000
#define NB_SCAN 98          // ceil(100000 / 1024)

// ---------------------------------------------------------------------------
// Scratch (__device__ globals; no allocations anywhere). Kernels receive all
// pointers as parameters (host resolves via cudaGetSymbolAddress).
// ---------------------------------------------------------------------------
__device__ float4 g_agg4[(size_t)N_NODES * 32];   // agg feats / YZ buffer
__device__ float4 g_hA4[(size_t)N_NODES * 32];    // hidden ping / h3
__device__ float4 g_hB4[(size_t)N_NODES * 32];    // hidden pong
__device__ float  g_whi[81920];                   // tf32-hi split weights
__device__ float  g_wlo[81920];                   // tf32-lo split weights
__device__ int    g_row_[N_NODES + 1];            // CSR row starts
__device__ int    g_csr_[N_EDGES];                // CSR col indices (src)
__device__ int    g_bsum_[NB_SCAN];               // scan block sums
__device__ int    g_flag_[1];                     // 1 = int64 edges, 0 = int32

// ---------------------------------------------------------------------------
// Weight split for 3xTF32: hi = top-10-mantissa truncation, lo = residual.
// ---------------------------------------------------------------------------
__global__ void w_split_kernel(const float* __restrict__ src,
                               float* __restrict__ hi, float* __restrict__ lo,
                               int n) {
    int i = blockIdx.x * blockDim.x + threadIdx.x;
    if (i < n) {
        float v = src[i];
        float h = __uint_as_float(__float_as_uint(v) & 0xFFFFE000u);
        hi[i] = h;
        lo[i] = v - h;
    }
}

// ---------------------------------------------------------------------------
// Edge dtype probe (JAX x64-disabled silently yields int32 despite int64
// annotation). int32 data read as int64 is out of [0,N) with overwhelming
// probability over 16 samples.
// ---------------------------------------------------------------------------
__global__ void detect_kernel(const void* __restrict__ ei, int* __restrict__ flag) {
    if (blockIdx.x == 0 && threadIdx.x == 0) {
        const long long* e64 = (const long long*)ei;
        int is64 = 1;
        for (int i = 0; i < 16; i++) {
            long long v = e64[i];
            if (v < 0 || v >= N_NODES) { is64 = 0; break; }
        }
        *flag = is64;
    }
}

__device__ __forceinline__ int2 load_edge(const void* __restrict__ ei, int e, int is64) {
    if (is64) {
        const long long* p = (const long long*)ei;
        return make_int2((int)p[e], (int)p[N_EDGES + e]);
    } else {
        const int* p = (const int*)ei;
        return make_int2(p[e], p[N_EDGES + e]);
    }
}

// ---------------------------------------------------------------------------
// CSR build. Atomics only on harness-allocated d_out scratch.
// ---------------------------------------------------------------------------
__global__ void zero_int_kernel(int* __restrict__ p, int n) {
    int i = blockIdx.x * blockDim.x + threadIdx.x;
    if (i < n) p[i] = 0;
}

__global__ void hist_kernel(const void* __restrict__ ei,
                            const int* __restrict__ flag,
                            int* __restrict__ cnt) {
    int e = blockIdx.x * blockDim.x + threadIdx.x;
    if (e < N_EDGES) {
        int2 sd = load_edge(ei, e, *flag);
        if ((unsigned)sd.x < N_NODES && (unsigned)sd.y < N_NODES)
            atomicAdd(&cnt[sd.y], 1);
    }
}

__global__ void scan_block_kernel(const int* __restrict__ cnt,
                                  int* __restrict__ row,
                                  int* __restrict__ bsum) {
    __shared__ int s[1024];
    int i = blockIdx.x * 1024 + threadIdx.x;
    int v = (i < N_NODES) ? cnt[i] : 0;
    s[threadIdx.x] = v;
    __syncthreads();
    for (int off = 1; off < 1024; off <<= 1) {
        int t = (threadIdx.x >= off) ? s[threadIdx.x - off] : 0;
        __syncthreads();
        s[threadIdx.x] += t;
        __syncthreads();
    }
    if (i < N_NODES) row[i] = s[threadIdx.x] - v;
    if (threadIdx.x == 1023) bsum[blockIdx.x] = s[1023];
}

__global__ void scan_bsum_kernel(int* __restrict__ bsum, int* __restrict__ row) {
    if (threadIdx.x == 0 && blockIdx.x == 0) {
        int acc = 0;
        for (int b = 0; b < NB_SCAN; b++) {
            int t = bsum[b];
            bsum[b] = acc;
            acc += t;
        }
        row[N_NODES] = acc;
    }
}

__global__ void scan_add_kernel(int* __restrict__ row,
                                const int* __restrict__ bsum) {
    int i = blockIdx.x * 1024 + threadIdx.x;
    if (i < N_NODES) row[i] += bsum[blockIdx.x];
}

__global__ void copy_int_kernel(const int* __restrict__ src,
                                int* __restrict__ dst, int n) {
    int i = blockIdx.x * blockDim.x + threadIdx.x;
    if (i < n) dst[i] = src[i];
}

__global__ void fill_kernel(const void* __restrict__ ei,
                            const int* __restrict__ flag,
                            int* __restrict__ cur,
                            int* __restrict__ csr) {
    int e = blockIdx.x * blockDim.x + threadIdx.x;
    if (e < N_EDGES) {
        int2 sd = load_edge(ei, e, *flag);
        if ((unsigned)sd.x < N_NODES && (unsigned)sd.y < N_NODES) {
            int pos = atomicAdd(&cur[sd.y], 1);
            if ((unsigned)pos < N_EDGES) csr[pos] = sd.x;
        }
    }
}

// ---------------------------------------------------------------------------
// Pull-mode aggregation (128-d): warp per node, float4 per lane, unroll 4.
// ---------------------------------------------------------------------------
__global__ void gather_kernel(const float4* __restrict__ feat4,
                              const int* __restrict__ row,
                              const int* __restrict__ csr,
                              float4* __restrict__ agg4) {
    int lane = threadIdx.x & 31;
    int n = (blockIdx.x * blockDim.x + threadIdx.x) >> 5;
    if (n >= N_NODES) return;
    int beg = row[n], end = row[n + 1];
    float4 a0 = make_float4(0.f,0.f,0.f,0.f), a1 = a0, a2 = a0, a3 = a0;
    int i = beg;
    for (; i + 3 < end; i += 4) {
        int s0 = csr[i], s1 = csr[i+1], s2 = csr[i+2], s3 = csr[i+3];
        float4 v0 = feat4[(size_t)s0 * 32 + lane];
        float4 v1 = feat4[(size_t)s1 * 32 + lane];
        float4 v2 = feat4[(size_t)s2 * 32 + lane];
        float4 v3 = feat4[(size_t)s3 * 32 + lane];
        a0.x += v0.x; a0.y += v0.y; a0.z += v0.z; a0.w += v0.w;
        a1.x += v1.x; a1.y += v1.y; a1.z += v1.z; a1.w += v1.w;
        a2.x += v2.x; a2.y += v2.y; a2.z += v2.z; a2.w += v2.w;
        a3.x += v3.x; a3.y += v3.y; a3.z += v3.z; a3.w += v3.w;
    }
    for (; i < end; i++) {
        int s0 = csr[i];
        float4 v0 = feat4[(size_t)s0 * 32 + lane];
        a0.x += v0.x; a0.y += v0.y; a0.z += v0.z; a0.w += v0.w;
    }
    a0.x += a1.x + a2.x + a3.x;
    a0.y += a1.y + a2.y + a3.y;
    a0.z += a1.z + a2.z + a3.z;
    a0.w += a1.w + a2.w + a3.w;
    int cnt = end - beg;
    float rd = 1.f / (float)(cnt > 0 ? cnt : 1);
    a0.x *= rd; a0.y *= rd; a0.z *= rd; a0.w *= rd;
    agg4[(size_t)n * 32 + lane] = a0;
}

// ---------------------------------------------------------------------------
// Layer-3 fused gather: h3 = relu( mean_nbr(YZ[:, :64]) + YZ[n, 64:128] ).
// Half-warp (16 lanes) per node; float4 per lane covers the 64-d row.
// ---------------------------------------------------------------------------
__global__ void gather_yz_kernel(const float4* __restrict__ yz4,
                                 const int* __restrict__ row,
                                 const int* __restrict__ csr,
                                 float4* __restrict__ h3_4) {
    int tid = blockIdx.x * blockDim.x + threadIdx.x;
    int n = tid >> 4;
    int l = tid & 15;
    if (n >= N_NODES) return;
    int beg = row[n], end = row[n + 1];
    float4 a0 = make_float4(0.f,0.f,0.f,0.f), a1 = a0;
    int i = beg;
    for (; i + 1 < end; i += 2) {
        int s0 = csr[i], s1 = csr[i+1];
        float4 v0 = yz4[(size_t)s0 * 32 + l];
        float4 v1 = yz4[(size_t)s1 * 32 + l];
        a0.x += v0.x; a0.y += v0.y; a0.z += v0.z; a0.w += v0.w;
        a1.x += v1.x; a1.y += v1.y; a1.z += v1.z; a1.w += v1.w;
    }
    for (; i < end; i++) {
        int s0 = csr[i];
        float4 v0 = yz4[(size_t)s0 * 32 + l];
        a0.x += v0.x; a0.y += v0.y; a0.z += v0.z; a0.w += v0.w;
    }
    a0.x += a1.x; a0.y += a1.y; a0.z += a1.z; a0.w += a1.w;
    int cnt = end - beg;
    float rd = 1.f / (float)(cnt > 0 ? cnt : 1);
    float4 z = yz4[(size_t)n * 32 + 16 + l];
    float4 r;
    r.x = fmaxf(a0.x * rd + z.x, 0.f);
    r.y = fmaxf(a0.y * rd + z.y, 0.f);
    r.z = fmaxf(a0.z * rd + z.z, 0.f);
    r.w = fmaxf(a0.w * rd + z.w, 0.f);
    h3_4[(size_t)n * 16 + l] = r;
}

// ---------------------------------------------------------------------------
// 3xTF32 tensor-core GEMM. BM=128, BN=128, KC=16 chunks; 8 warps as 4Mx2N,
// warp tile 32x64 (2 m16 x 8 n8 frags). D = sum_op A_op @ W_op^T (+bias,relu).
// CAT variant: single op (W = [Wl3;Wr3] concat), bias on cols >=64, no relu.
// smem row stride 20 -> conflict-free fragment loads (bank = 20r+c perm).
// ---------------------------------------------------------------------------
__device__ __forceinline__ void mma_tf32(float* c, const unsigned* a, const unsigned* b) {
    asm volatile(
        "mma.sync.aligned.m16n8k8.row.col.f32.tf32.tf32.f32 "
        "{%0,%1,%2,%3}, {%4,%5,%6,%7}, {%8,%9}, {%0,%1,%2,%3};\n"
        : "+f"(c[0]), "+f"(c[1]), "+f"(c[2]), "+f"(c[3])
        : "r"(a[0]), "r"(a[1]), "r"(a[2]), "r"(a[3]), "r"(b[0]), "r"(b[1]));
}

template <bool CAT>
__global__ __launch_bounds__(256) void sage_mma_kernel(
    const float* __restrict__ A0,      // agg (op0) or h2 (CAT)
    const float* __restrict__ A1,      // x   (op1), unused if CAT
    const float* __restrict__ wh0, const float* __restrict__ wl0,
    const float* __restrict__ wh1, const float* __restrict__ wl1,
    const float* __restrict__ bias,
    float* __restrict__ outp)
{
    __shared__ float Ah[128][20], Al[128][20], Wh[128][20], Wlo[128][20];

    const int tid  = threadIdx.x;
    const int lane = tid & 31;
    const int warp = tid >> 5;
    const int wm   = warp & 3;       // 0..3 (M)
    const int wn   = warp >> 2;      // 0..1 (N)
    const int g    = lane >> 2;      // 0..7
    const int t    = lane & 3;       // 0..3
    const int base = blockIdx.x * 128;

    float c[2][8][4];
#pragma unroll
    for (int mt = 0; mt < 2; mt++)
#pragma unroll
        for (int nt = 0; nt < 8; nt++)
#pragma unroll
            for (int k = 0; k < 4; k++) c[mt][nt][k] = 0.f;

    const int NOPS = CAT ? 1 : 2;
    for (int op = 0; op < NOPS; op++) {
        const float* Ap  = (op == 0) ? A0 : A1;
        const float* Whp = (op == 0) ? wh0 : wh1;
        const float* Wlp = (op == 0) ? wl0 : wl1;
        for (int kc = 0; kc < 8; kc++) {
            const int kb = kc * 16;
            __syncthreads();
            // stage A (hi/lo on the fly) and pre-split W
#pragma unroll
            for (int it = 0; it < 2; it++) {
                int i = tid + it * 256;           // 0..511
                int r = i >> 2;
                int q = (i & 3) << 2;             // 0,4,8,12
                int node = base + r;
                float4 v = make_float4(0.f,0.f,0.f,0.f);
                if (node < N_NODES) v = *(const float4*)(Ap + (size_t)node * 128 + kb + q);
                float4 hv, lv;
                hv.x = __uint_as_float(__float_as_uint(v.x) & 0xFFFFE000u); lv.x = v.x - hv.x;
                hv.y = __uint_as_float(__float_as_uint(v.y) & 0xFFFFE000u); lv.y = v.y - hv.y;
                hv.z = __uint_as_float(__float_as_uint(v.z) & 0xFFFFE000u); lv.z = v.z - hv.z;
                hv.w = __uint_as_float(__float_as_uint(v.w) & 0xFFFFE000u); lv.w = v.w - hv.w;
                *(float4*)&Ah[r][q] = hv;
                *(float4*)&Al[r][q] = lv;
                *(float4*)&Wh[r][q]  = *(const float4*)(Whp + (size_t)r * 128 + kb + q);
                *(float4*)&Wlo[r][q] = *(const float4*)(Wlp + (size_t)r * 128 + kb + q);
            }
            __syncthreads();
#pragma unroll
            for (int ks = 0; ks < 2; ks++) {
                const int kk = ks * 8;
                unsigned ah[2][4], al[2][4];
#pragma unroll
                for (int mt = 0; mt < 2; mt++) {
                    int r0 = wm * 32 + mt * 16 + g;
                    ah[mt][0] = __float_as_uint(Ah[r0    ][kk + t    ]);
                    ah[mt][1] = __float_as_uint(Ah[r0 + 8][kk + t    ]);
                    ah[mt][2] = __float_as_uint(Ah[r0    ][kk + t + 4]);
                    ah[mt][3] = __float_as_uint(Ah[r0 + 8][kk + t + 4]);
                    al[mt][0] = __float_as_uint(Al[r0    ][kk + t    ]);
                    al[mt][1] = __float_as_uint(Al[r0 + 8][kk + t    ]);
                    al[mt][2] = __float_as_uint(Al[r0    ][kk + t + 4]);
                    al[mt][3] = __float_as_uint(Al[r0 + 8][kk + t + 4]);
                }
                unsigned bh[8][2], bl[8][2];
#pragma unroll
                for (int nt = 0; nt < 8; nt++) {
                    int n0 = wn * 64 + nt * 8 + g;
                    bh[nt][0] = __float_as_uint(Wh[n0][kk + t    ]);
                    bh[nt][1] = __float_as_uint(Wh[n0][kk + t + 4]);
                    bl[nt][0] = __float_as_uint(Wlo[n0][kk + t    ]);
                    bl[nt][1] = __float_as_uint(Wlo[n0][kk + t + 4]);
                }
#pragma unroll
                for (int mt = 0; mt < 2; mt++)
#pragma unroll
                    for (int nt = 0; nt < 8; nt++) {
                        mma_tf32(c[mt][nt], ah[mt], bh[nt]);
                        mma_tf32(c[mt][nt], ah[mt], bl[nt]);
                        mma_tf32(c[mt][nt], al[mt], bh[nt]);
                    }
            }
        }
    }

    // epilogue
#pragma unroll
    for (int mt = 0; mt < 2; mt++) {
        int m0 = base + wm * 32 + mt * 16 + g;
#pragma unroll
        for (int nt = 0; nt < 8; nt++) {
            int n = wn * 64 + nt * 8 + 2 * t;
            float b0, b1;
            if (CAT) {
                b0 = (n     >= 64) ? bias[n     - 64] : 0.f;
                b1 = (n + 1 >= 64) ? bias[n + 1 - 64] : 0.f;
            } else {
                b0 = bias[n]; b1 = bias[n + 1];
            }
            float v0 = c[mt][nt][0] + b0;
            float v1 = c[mt][nt][1] + b1;
            float v2 = c[mt][nt][2] + b0;
            float v3 = c[mt][nt][3] + b1;
            if (!CAT) {
                v0 = fmaxf(v0, 0.f); v1 = fmaxf(v1, 0.f);
                v2 = fmaxf(v2, 0.f); v3 = fmaxf(v3, 0.f);
            }
            if (m0 < N_NODES)
                *(float2*)(outp + (size_t)m0 * 128 + n) = make_float2(v0, v1);
            if (m0 + 8 < N_NODES)
                *(float2*)(outp + (size_t)(m0 + 8) * 128 + n) = make_float2(v2, v3);
        }
    }
}

// ---------------------------------------------------------------------------
// Classifier: sigmoid(h3 @ Wc^T + bc). Warp per node, 2 features/lane.
// ---------------------------------------------------------------------------
__global__ void cls_kernel(const float* __restrict__ h,
                           const float* __restrict__ Wc,
                           const float* __restrict__ bc,
                           float* __restrict__ outp) {
    int lane = threadIdx.x & 31;
    int n = (blockIdx.x * blockDim.x + threadIdx.x) >> 5;
    if (n >= N_NODES) return;
    float w0 = Wc[lane * 2], w1 = Wc[lane * 2 + 1];
    float b = bc[0];
    const float* hp = h + (size_t)n * 64 + lane * 2;
    float s = hp[0] * w0 + hp[1] * w1;
#pragma unroll
    for (int o = 16; o > 0; o >>= 1) s += __shfl_xor_sync(0xffffffffu, s, o);
    if (lane == 0) outp[n] = 1.f / (1.f + expf(-(s + b)));
}

// ---------------------------------------------------------------------------
// Launch. d_out doubles as int scratch during CSR build, overwritten at end.
// ---------------------------------------------------------------------------
extern "C" void kernel_launch(void* const* d_in, const int* in_sizes, int n_in,
                              void* d_out, int out_size) {
    const float* x   = (const float*)d_in[0];
    const void*  ei  = d_in[1];               // int32 or int64, probed at runtime
    const float* Wl1 = (const float*)d_in[2];
    const float* bl1 = (const float*)d_in[3];
    const float* Wr1 = (const float*)d_in[4];
    const float* Wl2 = (const float*)d_in[5];
    const float* bl2 = (const float*)d_in[6];
    const float* Wr2 = (const float*)d_in[7];
    const float* Wl3 = (const float*)d_in[8];
    const float* bl3 = (const float*)d_in[9];
    const float* Wr3 = (const float*)d_in[10];
    const float* Wc  = (const float*)d_in[11];
    const float* bc  = (const float*)d_in[12];

    void *p_agg=0, *p_hA=0, *p_hB=0, *p_row=0, *p_csr=0, *p_bsum=0, *p_flag=0, *p_whi=0, *p_wlo=0;
    cudaGetSymbolAddress(&p_agg,  g_agg4);
    cudaGetSymbolAddress(&p_hA,   g_hA4);
    cudaGetSymbolAddress(&p_hB,   g_hB4);
    cudaGetSymbolAddress(&p_row,  g_row_);
    cudaGetSymbolAddress(&p_csr,  g_csr_);
    cudaGetSymbolAddress(&p_bsum, g_bsum_);
    cudaGetSymbolAddress(&p_flag, g_flag_);
    cudaGetSymbolAddress(&p_whi,  g_whi);
    cudaGetSymbolAddress(&p_wlo,  g_wlo);

    float4* agg4 = (float4*)p_agg;
    float4* hA4  = (float4*)p_hA;
    float4* hB4  = (float4*)p_hB;
    float*  aggf = (float*)p_agg;
    float*  hAf  = (float*)p_hA;
    float*  hBf  = (float*)p_hB;
    float*  whi  = (float*)p_whi;
    float*  wlo  = (float*)p_wlo;
    int*    row  = (int*)p_row;
    int*    csr  = (int*)p_csr;
    int*    bsum = (int*)p_bsum;
    int*    flag = (int*)p_flag;
    int*    scr  = (int*)d_out;
    float*  out  = (float*)d_out;

    const int EB  = (N_EDGES + 255) / 256;
    const int NB  = (N_NODES + 255) / 256;
    const int WNB = (N_NODES * 32 + 255) / 256;       // warp per node
    const int HNB = (N_NODES * 16 + 255) / 256;       // half-warp per node
    const int GMB = (N_NODES + 127) / 128;            // 128-node GEMM tiles

    // weight hi/lo splits (layer3 concatenated [Wl3;Wr3] at offset 65536)
    w_split_kernel<<<64, 256>>>(Wl1, whi + 0,     wlo + 0,     16384);
    w_split_kernel<<<64, 256>>>(Wr1, whi + 16384, wlo + 16384, 16384);
    w_split_kernel<<<64, 256>>>(Wl2, whi + 32768, wlo + 32768, 16384);
    w_split_kernel<<<64, 256>>>(Wr2, whi + 49152, wlo + 49152, 16384);
    w_split_kernel<<<32, 256>>>(Wl3, whi + 65536, wlo + 65536, 8192);
    w_split_kernel<<<32, 256>>>(Wr3, whi + 73728, wlo + 73728, 8192);

    // edge dtype probe + CSR build (atomics only on scr / d_out)
    detect_kernel<<<1, 32>>>(ei, flag);
    zero_int_kernel<<<NB, 256>>>(scr, N_NODES);
    hist_kernel<<<EB, 256>>>(ei, flag, scr);
    scan_block_kernel<<<NB_SCAN, 1024>>>(scr, row, bsum);
    scan_bsum_kernel<<<1, 32>>>(bsum, row);
    scan_add_kernel<<<NB_SCAN, 1024>>>(row, bsum);
    copy_int_kernel<<<NB, 256>>>(row, scr, N_NODES);
    fill_kernel<<<EB, 256>>>(ei, flag, scr, csr);

    // layer 1: x -> hA
    gather_kernel<<<WNB, 256>>>((const float4*)x, row, csr, agg4);
    sage_mma_kernel<false><<<GMB, 256>>>(aggf, x, whi + 0, wlo + 0,
                                         whi + 16384, wlo + 16384, bl1, hAf);

    // layer 2: hA -> hB
    gather_kernel<<<WNB, 256>>>(hA4, row, csr, agg4);
    sage_mma_kernel<false><<<GMB, 256>>>(aggf, hAf, whi + 32768, wlo + 32768,
                                         whi + 49152, wlo + 49152, bl2, hBf);

    // layer 3: YZ = h2 @ [Wl3;Wr3]^T  (Z cols get bias, no relu), then
    // fused gather: h3 = relu(mean_nbr(Y) + Z)  -> hA
    sage_mma_kernel<true><<<GMB, 256>>>(hBf, hBf, whi + 65536, wlo + 65536,
                                        whi + 65536, wlo + 65536, bl3, aggf);
    gather_yz_kernel<<<HNB, 256>>>(agg4, row, csr, hA4);

    // classifier overwrites d_out
    cls_kernel<<<WNB, 256>>>(hAf, Wc, bc, out);
}